// round 5
// baseline (speedup 1.0000x reference)
#include <cuda_runtime.h>
#include <cuda_bf16.h>
#include <cstdint>

#define B_   256
#define N_   144
#define M_   (B_ * N_)            // 36864 rows
#define SCALE_ 0.125f             // 64^-0.5

// ---------------- scratch (device globals: allocation-free rule) -------------
__device__ float g_kv [(size_t)M_ * 1024];   // [m, {k|v}], col = h*64+e
__device__ float g_q  [(size_t)M_ * 512];
__device__ float g_att[(size_t)M_ * 512];

// ---------------- helpers ------------------------------------------------------
__device__ __forceinline__ uint32_t smem_u32(const void* p) {
    uint32_t a;
    asm("{ .reg .u64 t; cvta.to.shared.u64 t, %1; cvt.u32.u64 %0, t; }" : "=r"(a) : "l"(p));
    return a;
}
__device__ __forceinline__ void ldsm_x4(uint32_t& r0, uint32_t& r1, uint32_t& r2,
                                        uint32_t& r3, uint32_t addr) {
    asm volatile("ldmatrix.sync.aligned.m8n8.x4.shared.b16 {%0,%1,%2,%3}, [%4];"
                 : "=r"(r0), "=r"(r1), "=r"(r2), "=r"(r3) : "r"(addr));
}
__device__ __forceinline__ void mma_bf16(float* c, uint32_t a0, uint32_t a1,
                                         uint32_t a2, uint32_t a3,
                                         uint32_t b0, uint32_t b1) {
    asm volatile(
        "mma.sync.aligned.m16n8k16.row.col.f32.bf16.bf16.f32 "
        "{%0,%1,%2,%3}, {%4,%5,%6,%7}, {%8,%9}, {%0,%1,%2,%3};"
        : "+f"(c[0]), "+f"(c[1]), "+f"(c[2]), "+f"(c[3])
        : "r"(a0), "r"(a1), "r"(a2), "r"(a3), "r"(b0), "r"(b1));
}
// split float4 -> hi pair (2x bf16x2) and lo pair
__device__ __forceinline__ void split4(float4 f, uint32_t& h01, uint32_t& h23,
                                       uint32_t& l01, uint32_t& l23) {
    __nv_bfloat16 hx = __float2bfloat16_rn(f.x);
    __nv_bfloat16 hy = __float2bfloat16_rn(f.y);
    __nv_bfloat16 hz = __float2bfloat16_rn(f.z);
    __nv_bfloat16 hw = __float2bfloat16_rn(f.w);
    __nv_bfloat162 h0 = __nv_bfloat162(hx, hy);
    __nv_bfloat162 h1 = __nv_bfloat162(hz, hw);
    h01 = *reinterpret_cast<uint32_t*>(&h0);
    h23 = *reinterpret_cast<uint32_t*>(&h1);
    __nv_bfloat162 l0 = __nv_bfloat162(
        __float2bfloat16_rn(f.x - __bfloat162float(hx)),
        __float2bfloat16_rn(f.y - __bfloat162float(hy)));
    __nv_bfloat162 l1 = __nv_bfloat162(
        __float2bfloat16_rn(f.z - __bfloat162float(hz)),
        __float2bfloat16_rn(f.w - __bfloat162float(hw)));
    l01 = *reinterpret_cast<uint32_t*>(&l0);
    l23 = *reinterpret_cast<uint32_t*>(&l1);
}
__device__ __forceinline__ void sts128(uint32_t addr, uint32_t a, uint32_t b,
                                       uint32_t c, uint32_t d) {
    asm volatile("st.shared.v4.b32 [%0], {%1,%2,%3,%4};"
                 :: "r"(addr), "r"(a), "r"(b), "r"(c), "r"(d) : "memory");
}

// ---------------- mma.sync bf16-split GEMM, fp32 in / fp32 out -----------------
// C[M x Nc] = (A (+ f*A2)) @ W^T (+ bias);  A:[M,512], W:[Nc,512] fp32 row-major.
// In-register hi/lo split -> 4 smem tiles per 64-wide K chunk -> 3 MMA passes
// (AhiBhi + AloBhi + AhiBlo), fp32 accumulate.  CTA 128x128, 8 warps 64x32.
#define GPITCH   144                       // bytes per smem row (72 bf16)
#define TILE_B   (128 * GPITCH)            // 18432 bytes per tile
#define BUF_B    (4 * TILE_B)              // Ahi,Alo,Bhi,Blo
#define GEMM_SMEM (2 * BUF_B)              // 147456 double-buffered

template<bool HAS_A2>
__global__ __launch_bounds__(256)
void gemm_mma_kernel(const float* __restrict__ A, const float* __restrict__ A2,
                     const int* __restrict__ flag,
                     const float* __restrict__ W, const float* __restrict__ bias,
                     float* __restrict__ C, int Nc)
{
    extern __shared__ __align__(128) char smem[];
    const uint32_t sbase = smem_u32(smem);

    const int t    = threadIdx.x;
    const int lane = t & 31;
    const int w    = t >> 5;
    const int wm   = w >> 2;
    const int wn   = w & 3;
    const int row0 = blockIdx.y * 128;
    const int col0 = blockIdx.x * 128;

    float addf = 0.f;
    if (HAS_A2) addf = (*flag != 0) ? 1.f : 0.f;

    // ldmatrix lane addresses (within a tile)
    const uint32_t aOff = (uint32_t)(wm * 64 + (lane & 15)) * GPITCH + (lane >> 4) * 16;
    const uint32_t bOff = (uint32_t)(wn * 32 + (lane & 7) + ((lane >> 4) & 1) * 8) * GPITCH
                        + ((lane >> 3) & 1) * 16;

    float acc[4][4][4];
#pragma unroll
    for (int mi = 0; mi < 4; mi++)
#pragma unroll
        for (int nj = 0; nj < 4; nj++)
#pragma unroll
            for (int e = 0; e < 4; e++) acc[mi][nj][e] = 0.f;

    // staging: thread -> row r = t>>1 (0..127), half h = t&1 (32 cols)
    const int r = t >> 1;
    const int h = t & 1;
    const float* Ar  = A + (size_t)(row0 + r) * 512 + h * 32;
    const float* A2r = HAS_A2 ? (A2 + (size_t)(row0 + r) * 512 + h * 32) : nullptr;
    const float* Br  = W + (size_t)(col0 + r) * 512 + h * 32;
    const uint32_t stA = sbase + (uint32_t)r * GPITCH + h * 64;   // + tile offset
    const uint32_t stB = stA + 2 * TILE_B;

    float4 av[8], bv[8];
    // prologue: load + stage chunk 0 into buffer 0
#pragma unroll
    for (int j = 0; j < 8; j++) {
        av[j] = *(const float4*)(Ar + j * 4);
        bv[j] = *(const float4*)(Br + j * 4);
        if (HAS_A2) {
            float4 tp = *(const float4*)(A2r + j * 4);
            av[j].x += addf * tp.x; av[j].y += addf * tp.y;
            av[j].z += addf * tp.z; av[j].w += addf * tp.w;
        }
    }
#pragma unroll
    for (int jj = 0; jj < 4; jj++) {
        uint32_t h0, h1, h2, h3, l0, l1, l2, l3;
        split4(av[2 * jj],     h0, h1, l0, l1);
        split4(av[2 * jj + 1], h2, h3, l2, l3);
        sts128(stA + jj * 16,          h0, h1, h2, h3);
        sts128(stA + TILE_B + jj * 16, l0, l1, l2, l3);
        split4(bv[2 * jj],     h0, h1, l0, l1);
        split4(bv[2 * jj + 1], h2, h3, l2, l3);
        sts128(stB + jj * 16,          h0, h1, h2, h3);
        sts128(stB + TILE_B + jj * 16, l0, l1, l2, l3);
    }
    __syncthreads();

    for (int c = 0; c < 8; c++) {
        const uint32_t bufB = (uint32_t)(c & 1) * BUF_B;
        // prefetch next chunk's fp32 (hides under the MMA section)
        if (c < 7) {
            const int k0 = (c + 1) * 64;
#pragma unroll
            for (int j = 0; j < 8; j++) {
                av[j] = *(const float4*)(Ar + k0 + j * 4);
                bv[j] = *(const float4*)(Br + k0 + j * 4);
                if (HAS_A2) {
                    float4 tp = *(const float4*)(A2r + k0 + j * 4);
                    av[j].x += addf * tp.x; av[j].y += addf * tp.y;
                    av[j].z += addf * tp.z; av[j].w += addf * tp.w;
                }
            }
        }
        // 3 passes: (Ahi,Bhi), (Alo,Bhi), (Ahi,Blo)
#pragma unroll
        for (int p = 0; p < 3; p++) {
            const uint32_t aT = sbase + bufB + ((p == 1) ? TILE_B : 0) + aOff;
            const uint32_t bT = sbase + bufB + 2 * TILE_B + ((p == 2) ? TILE_B : 0) + bOff;
#pragma unroll
            for (int ks = 0; ks < 4; ks++) {
                uint32_t ar[4][4], br[2][4];
#pragma unroll
                for (int mi = 0; mi < 4; mi++)
                    ldsm_x4(ar[mi][0], ar[mi][1], ar[mi][2], ar[mi][3],
                            aT + (uint32_t)mi * 16 * GPITCH + ks * 32);
#pragma unroll
                for (int pj = 0; pj < 2; pj++)
                    ldsm_x4(br[pj][0], br[pj][1], br[pj][2], br[pj][3],
                            bT + (uint32_t)pj * 16 * GPITCH + ks * 32);
#pragma unroll
                for (int mi = 0; mi < 4; mi++)
#pragma unroll
                    for (int nj = 0; nj < 4; nj++) {
                        const int pj = nj >> 1, hb = (nj & 1) * 2;
                        mma_bf16(acc[mi][nj], ar[mi][0], ar[mi][1], ar[mi][2], ar[mi][3],
                                 br[pj][hb], br[pj][hb + 1]);
                    }
            }
        }
        // stage next chunk into the other buffer
        if (c < 7) {
            const uint32_t nb = (uint32_t)((c + 1) & 1) * BUF_B;
            const uint32_t dA = stA + nb;
            const uint32_t dB = stB + nb;
#pragma unroll
            for (int jj = 0; jj < 4; jj++) {
                uint32_t h0, h1, h2, h3, l0, l1, l2, l3;
                split4(av[2 * jj],     h0, h1, l0, l1);
                split4(av[2 * jj + 1], h2, h3, l2, l3);
                sts128(dA + jj * 16,          h0, h1, h2, h3);
                sts128(dA + TILE_B + jj * 16, l0, l1, l2, l3);
                split4(bv[2 * jj],     h0, h1, l0, l1);
                split4(bv[2 * jj + 1], h2, h3, l2, l3);
                sts128(dB + jj * 16,          h0, h1, h2, h3);
                sts128(dB + TILE_B + jj * 16, l0, l1, l2, l3);
            }
        }
        __syncthreads();
    }

    // epilogue
    const int rbase = row0 + wm * 64 + (lane >> 2);
    const int cbase = col0 + wn * 32 + (lane & 3) * 2;
#pragma unroll
    for (int mi = 0; mi < 4; mi++) {
#pragma unroll
        for (int nj = 0; nj < 4; nj++) {
            const int rr = rbase + mi * 16;
            const int cc = cbase + nj * 8;
            float b0 = 0.f, b1 = 0.f;
            if (bias) { b0 = bias[cc]; b1 = bias[cc + 1]; }
            *(float2*)(C + (size_t)rr * Nc + cc) =
                make_float2(acc[mi][nj][0] + b0, acc[mi][nj][1] + b1);
            *(float2*)(C + (size_t)(rr + 8) * Nc + cc) =
                make_float2(acc[mi][nj][2] + b0, acc[mi][nj][3] + b1);
        }
    }
}

// ---------------- attention (unchanged from round 3/4) ------------------------
#define AP   145
#define VP   68
#define QT_OFF 0
#define KT_OFF (64 * AP)
#define V_OFF  (2 * 64 * AP)
#define PT_OFF (2 * 64 * AP + 144 * VP)
#define ATTN_SMEM_FLOATS (2 * 64 * AP + 144 * VP + 144 * AP)
#define ATTN_SMEM_BYTES  (ATTN_SMEM_FLOATS * 4)

__global__ __launch_bounds__(256, 1)
void attn_kernel(const float* __restrict__ q, const float* __restrict__ kv,
                 float* __restrict__ o)
{
    extern __shared__ float sm[];
    float* Qt = sm + QT_OFF;
    float* Kt = sm + KT_OFF;
    float* Vs = sm + V_OFF;
    float* Pt = sm + PT_OFF;
    float* red = Pt;

    const int b = blockIdx.x >> 3;
    const int h = blockIdx.x & 7;
    const int t = threadIdx.x;
    const int ty = t >> 4;
    const int tx = t & 15;

    const float* qb = q  + (size_t)b * 144 * 512  + h * 64;
    const float* kb = kv + (size_t)b * 144 * 1024 + h * 64;
    const float* vb = kb + 512;

    for (int i = t; i < 144 * 64; i += 256) {
        int r = i >> 6, k = i & 63;
        Qt[k * AP + r] = qb[(size_t)r * 512 + k] * SCALE_;
        Kt[k * AP + r] = kb[(size_t)r * 1024 + k];
    }
    for (int i = t; i < 144 * 16; i += 256) {
        int n = i >> 4, cc = (i & 15) << 2;
        *(float4*)(Vs + n * VP + cc) = *(const float4*)(vb + (size_t)n * 1024 + cc);
    }
    __syncthreads();

    float acc[9][9];
#pragma unroll
    for (int i = 0; i < 9; i++)
#pragma unroll
        for (int j = 0; j < 9; j++) acc[i][j] = 0.f;

    const float* Qb = Qt + ty * 9;
    const float* Kb = Kt + tx * 9;
#pragma unroll 2
    for (int k = 0; k < 64; k++) {
        float qv[9], kvv[9];
#pragma unroll
        for (int i = 0; i < 9; i++) qv[i]  = Qb[k * AP + i];
#pragma unroll
        for (int j = 0; j < 9; j++) kvv[j] = Kb[k * AP + j];
#pragma unroll
        for (int i = 0; i < 9; i++)
#pragma unroll
            for (int j = 0; j < 9; j++) acc[i][j] += qv[i] * kvv[j];
    }

#pragma unroll
    for (int i = 0; i < 9; i++) {
        float m = acc[i][0];
#pragma unroll
        for (int j = 1; j < 9; j++) m = fmaxf(m, acc[i][j]);
        red[(ty * 9 + i) * 17 + tx] = m;
    }
    __syncthreads();
    float mrow[9];
#pragma unroll
    for (int i = 0; i < 9; i++) {
        const float* rr = red + (ty * 9 + i) * 17;
        float m = rr[0];
#pragma unroll
        for (int u = 1; u < 16; u++) m = fmaxf(m, rr[u]);
        mrow[i] = m;
    }
    __syncthreads();
#pragma unroll
    for (int i = 0; i < 9; i++) {
        float s = 0.f;
#pragma unroll
        for (int j = 0; j < 9; j++) {
            float e = __expf(acc[i][j] - mrow[i]);
            acc[i][j] = e;
            s += e;
        }
        red[(ty * 9 + i) * 17 + tx] = s;
    }
    __syncthreads();
    float inv[9];
#pragma unroll
    for (int i = 0; i < 9; i++) {
        const float* rr = red + (ty * 9 + i) * 17;
        float s = rr[0];
#pragma unroll
        for (int u = 1; u < 16; u++) s += rr[u];
        inv[i] = 1.f / s;
    }
    __syncthreads();

#pragma unroll
    for (int j = 0; j < 9; j++)
#pragma unroll
        for (int i = 0; i < 9; i++)
            Pt[(tx * 9 + j) * AP + (ty * 9 + i)] = acc[i][j];
    __syncthreads();

    float out[9][4];
#pragma unroll
    for (int i = 0; i < 9; i++)
#pragma unroll
        for (int d = 0; d < 4; d++) out[i][d] = 0.f;

    const float* Pb = Pt + ty * 9;
#pragma unroll 2
    for (int j = 0; j < 144; j++) {
        float pv[9];
#pragma unroll
        for (int i = 0; i < 9; i++) pv[i] = Pb[j * AP + i];
        float4 vv = *(const float4*)(Vs + j * VP + tx * 4);
#pragma unroll
        for (int i = 0; i < 9; i++) {
            out[i][0] += pv[i] * vv.x;
            out[i][1] += pv[i] * vv.y;
            out[i][2] += pv[i] * vv.z;
            out[i][3] += pv[i] * vv.w;
        }
    }

    float* ob = o + (size_t)b * 144 * 512 + h * 64;
#pragma unroll
    for (int i = 0; i < 9; i++) {
        int r = ty * 9 + i;
        *(float4*)(ob + (size_t)r * 512 + tx * 4) =
            make_float4(out[i][0] * inv[i], out[i][1] * inv[i],
                        out[i][2] * inv[i], out[i][3] * inv[i]);
    }
}

// ---------------- launch -------------------------------------------------------
extern "C" void kernel_launch(void* const* d_in, const int* in_sizes, int n_in,
                              void* d_out, int out_size)
{
    const float* x      = (const float*)d_in[0];
    const float* topo   = (const float*)d_in[1];
    const float* kv_w   = (const float*)d_in[2];
    const float* q_w    = (const float*)d_in[3];
    const float* proj_w = (const float*)d_in[4];
    const float* proj_b = (const float*)d_in[5];
    const int*   is_end = (const int*)d_in[6];

    void *pkv, *pq, *patt;
    cudaGetSymbolAddress(&pkv,  g_kv);
    cudaGetSymbolAddress(&pq,   g_q);
    cudaGetSymbolAddress(&patt, g_att);

    cudaFuncSetAttribute(attn_kernel, cudaFuncAttributeMaxDynamicSharedMemorySize,
                         ATTN_SMEM_BYTES);
    cudaFuncSetAttribute(gemm_mma_kernel<true>,
                         cudaFuncAttributeMaxDynamicSharedMemorySize, GEMM_SMEM);
    cudaFuncSetAttribute(gemm_mma_kernel<false>,
                         cudaFuncAttributeMaxDynamicSharedMemorySize, GEMM_SMEM);

    // KV = (x + is_end*topo) @ kv_w^T   [36864 x 1024]
    gemm_mma_kernel<true><<<dim3(8, 288), 256, GEMM_SMEM>>>(
        x, topo, is_end, kv_w, nullptr, (float*)pkv, 1024);
    // Q = x @ q_w^T                      [36864 x 512]
    gemm_mma_kernel<false><<<dim3(4, 288), 256, GEMM_SMEM>>>(
        x, nullptr, nullptr, q_w, nullptr, (float*)pq, 512);
    // attention -> g_att [b,n,h,e]
    attn_kernel<<<B_ * 8, 256, ATTN_SMEM_BYTES>>>((float*)pq, (float*)pkv, (float*)patt);
    // out = att @ proj_w^T + proj_b
    gemm_mma_kernel<false><<<dim3(4, 288), 256, GEMM_SMEM>>>(
        (float*)patt, nullptr, nullptr, proj_w, proj_b, (float*)d_out, 512);
}

// round 6
// speedup vs baseline: 1.3400x; 1.3400x over previous
#include <cuda_runtime.h>
#include <cuda_bf16.h>
#include <cstdint>

#define B_   256
#define N_   144
#define M_   (B_ * N_)            // 36864 rows
#define SCALE_ 0.125f             // 64^-0.5

// ---------------- scratch (device globals: allocation-free rule) -------------
__device__ float g_kv [(size_t)M_ * 1024];
__device__ float g_q  [(size_t)M_ * 512];
__device__ float g_att[(size_t)M_ * 512];

// bf16 hi|lo split operands: [rows, 1024] = [hi(512) | lo(512)]
__device__ __nv_bfloat16 g_xte [(size_t)M_ * 1024];   // x + is_end*topo
__device__ __nv_bfloat16 g_xe  [(size_t)M_ * 1024];   // x
__device__ __nv_bfloat16 g_ae  [(size_t)M_ * 1024];   // attention out
__device__ __nv_bfloat16 g_wkve[(size_t)1024 * 1024];
__device__ __nv_bfloat16 g_wqe [(size_t)512 * 1024];
__device__ __nv_bfloat16 g_wpe [(size_t)512 * 1024];

// ---------------- helpers ------------------------------------------------------
__device__ __forceinline__ uint32_t smem_u32(const void* p) {
    uint32_t a;
    asm("{ .reg .u64 t; cvta.to.shared.u64 t, %1; cvt.u32.u64 %0, t; }" : "=r"(a) : "l"(p));
    return a;
}
__device__ __forceinline__ void ldsm_x4(uint32_t& r0, uint32_t& r1, uint32_t& r2,
                                        uint32_t& r3, uint32_t addr) {
    asm volatile("ldmatrix.sync.aligned.m8n8.x4.shared.b16 {%0,%1,%2,%3}, [%4];"
                 : "=r"(r0), "=r"(r1), "=r"(r2), "=r"(r3) : "r"(addr));
}
__device__ __forceinline__ void mma_bf16(float* c, uint32_t a0, uint32_t a1,
                                         uint32_t a2, uint32_t a3,
                                         uint32_t b0, uint32_t b1) {
    asm volatile(
        "mma.sync.aligned.m16n8k16.row.col.f32.bf16.bf16.f32 "
        "{%0,%1,%2,%3}, {%4,%5,%6,%7}, {%8,%9}, {%0,%1,%2,%3};"
        : "+f"(c[0]), "+f"(c[1]), "+f"(c[2]), "+f"(c[3])
        : "r"(a0), "r"(a1), "r"(a2), "r"(a3), "r"(b0), "r"(b1));
}
__device__ __forceinline__ void split1(float v, __nv_bfloat16& h, __nv_bfloat16& l) {
    h = __float2bfloat16_rn(v);
    l = __float2bfloat16_rn(v - __bfloat162float(h));
}
// packed f32x2
__device__ __forceinline__ unsigned long long pack2(float lo, float hi) {
    unsigned long long r;
    asm("mov.b64 %0, {%1, %2};" : "=l"(r) : "f"(lo), "f"(hi));
    return r;
}
__device__ __forceinline__ void fma2(unsigned long long& d, unsigned long long a, unsigned long long b) {
    asm("fma.rn.f32x2 %0, %1, %2, %0;" : "+l"(d) : "l"(a), "l"(b));
}
__device__ __forceinline__ float2 unpack2(unsigned long long v) {
    float2 r;
    asm("mov.b64 {%0, %1}, %2;" : "=f"(r.x), "=f"(r.y) : "l"(v));
    return r;
}

// ---------------- fp32 -> bf16 hi/lo split (single stream) --------------------
__global__ __launch_bounds__(256)
void split_bf16_kernel(const float4* __restrict__ in, __nv_bfloat16* __restrict__ out,
                       long total4)
{
    long i = (long)blockIdx.x * blockDim.x + threadIdx.x;
    if (i >= total4) return;
    float4 a = in[i];
    long idx = i * 4;
    long row = idx >> 9;
    int  col = (int)(idx & 511);
    float v[4] = { a.x, a.y, a.z, a.w };
    __nv_bfloat16 h[4], l[4];
#pragma unroll
    for (int j = 0; j < 4; j++) split1(v[j], h[j], l[j]);
    __nv_bfloat16* base = out + row * 1024 + col;
    *(uint2*)(base)       = *(uint2*)h;
    *(uint2*)(base + 512) = *(uint2*)l;
}

// dual: oxe = split(x), oxte = split(x + f*topo)
__global__ __launch_bounds__(256)
void split_dual_kernel(const float4* __restrict__ x, const float4* __restrict__ topo,
                       const int* __restrict__ flag,
                       __nv_bfloat16* __restrict__ oxe, __nv_bfloat16* __restrict__ oxte,
                       long total4)
{
    long i = (long)blockIdx.x * blockDim.x + threadIdx.x;
    if (i >= total4) return;
    float4 a = x[i];
    float4 tp = topo[i];
    float f = (*flag != 0) ? 1.f : 0.f;
    long idx = i * 4;
    long row = idx >> 9;
    int  col = (int)(idx & 511);
    float v1[4] = { a.x, a.y, a.z, a.w };
    float v2[4] = { a.x + f * tp.x, a.y + f * tp.y, a.z + f * tp.z, a.w + f * tp.w };
    __nv_bfloat16 h[4], l[4];
#pragma unroll
    for (int j = 0; j < 4; j++) split1(v1[j], h[j], l[j]);
    __nv_bfloat16* b1 = oxe + row * 1024 + col;
    *(uint2*)(b1)       = *(uint2*)h;
    *(uint2*)(b1 + 512) = *(uint2*)l;
#pragma unroll
    for (int j = 0; j < 4; j++) split1(v2[j], h[j], l[j]);
    __nv_bfloat16* b2 = oxte + row * 1024 + col;
    *(uint2*)(b2)       = *(uint2*)h;
    *(uint2*)(b2 + 512) = *(uint2*)l;
}

// ---------------- mma.sync bf16 GEMM (exact round-4 version) -------------------
#define GP 72

__global__ __launch_bounds__(256)
void gemm_mma_kernel(const __nv_bfloat16* __restrict__ A,
                     const __nv_bfloat16* __restrict__ Bw,
                     const float* __restrict__ bias,
                     float* __restrict__ C, int Nc)
{
    __shared__ __nv_bfloat16 sA[128 * GP];
    __shared__ __nv_bfloat16 sB[128 * GP];

    const int t    = threadIdx.x;
    const int lane = t & 31;
    const int w    = t >> 5;
    const int wm   = w >> 2;
    const int wn   = w & 3;
    const int row0 = blockIdx.y * 128;
    const int col0 = blockIdx.x * 128;

    const uint32_t sAu = smem_u32(sA);
    const uint32_t sBu = smem_u32(sB);

    const uint32_t aLane = sAu + (uint32_t)(wm * 64 + (lane & 15)) * 144 + (lane >> 4) * 16;
    const uint32_t bLane = sBu + (uint32_t)(wn * 32 + (lane & 7) + ((lane >> 4) & 1) * 8) * 144
                               + ((lane >> 3) & 1) * 16;

    float acc[4][4][4];
#pragma unroll
    for (int mi = 0; mi < 4; mi++)
#pragma unroll
        for (int nj = 0; nj < 4; nj++)
#pragma unroll
            for (int e = 0; e < 4; e++) acc[mi][nj][e] = 0.f;

    const int rowT = t >> 3;
    const int chT  = t & 7;
    const __nv_bfloat16* Ag = A  + (size_t)(row0 + rowT) * 1024 + chT * 8;
    const __nv_bfloat16* Bg = Bw + (size_t)(col0 + rowT) * 1024 + chT * 8;
    const uint32_t sAst = sAu + (uint32_t)rowT * 144 + chT * 16;
    const uint32_t sBst = sBu + (uint32_t)rowT * 144 + chT * 16;

    for (int c = 0; c < 24; c++) {
        const int s  = c >> 3;
        const int k0 = (c & 7) * 64;
        const int aCol = ((s == 1) ? 512 : 0) + k0;
        const int bCol = ((s == 2) ? 512 : 0) + k0;
        uint4 av[4], bv[4];
#pragma unroll
        for (int j = 0; j < 4; j++) {
            av[j] = *(const uint4*)(Ag + (size_t)j * 32 * 1024 + aCol);
            bv[j] = *(const uint4*)(Bg + (size_t)j * 32 * 1024 + bCol);
        }
        __syncthreads();
#pragma unroll
        for (int j = 0; j < 4; j++) {
            asm volatile("st.shared.v4.b32 [%0], {%1,%2,%3,%4};"
                :: "r"(sAst + j * 32 * 144), "r"(av[j].x), "r"(av[j].y), "r"(av[j].z), "r"(av[j].w)
                : "memory");
            asm volatile("st.shared.v4.b32 [%0], {%1,%2,%3,%4};"
                :: "r"(sBst + j * 32 * 144), "r"(bv[j].x), "r"(bv[j].y), "r"(bv[j].z), "r"(bv[j].w)
                : "memory");
        }
        __syncthreads();

#pragma unroll
        for (int ks = 0; ks < 4; ks++) {
            uint32_t ar[4][4], br[2][4];
#pragma unroll
            for (int mi = 0; mi < 4; mi++)
                ldsm_x4(ar[mi][0], ar[mi][1], ar[mi][2], ar[mi][3],
                        aLane + (uint32_t)mi * 16 * 144 + ks * 32);
#pragma unroll
            for (int pj = 0; pj < 2; pj++)
                ldsm_x4(br[pj][0], br[pj][1], br[pj][2], br[pj][3],
                        bLane + (uint32_t)pj * 16 * 144 + ks * 32);
#pragma unroll
            for (int mi = 0; mi < 4; mi++)
#pragma unroll
                for (int nj = 0; nj < 4; nj++) {
                    const int pj = nj >> 1, hb = (nj & 1) * 2;
                    mma_bf16(acc[mi][nj], ar[mi][0], ar[mi][1], ar[mi][2], ar[mi][3],
                             br[pj][hb], br[pj][hb + 1]);
                }
        }
    }

    const int rbase = row0 + wm * 64 + (lane >> 2);
    const int cbase = col0 + wn * 32 + (lane & 3) * 2;
#pragma unroll
    for (int mi = 0; mi < 4; mi++) {
#pragma unroll
        for (int nj = 0; nj < 4; nj++) {
            const int r  = rbase + mi * 16;
            const int cc = cbase + nj * 8;
            float b0 = 0.f, b1 = 0.f;
            if (bias) { b0 = bias[cc]; b1 = bias[cc + 1]; }
            *(float2*)(C + (size_t)r * Nc + cc) =
                make_float2(acc[mi][nj][0] + b0, acc[mi][nj][1] + b1);
            *(float2*)(C + (size_t)(r + 8) * Nc + cc) =
                make_float2(acc[mi][nj][2] + b0, acc[mi][nj][3] + b1);
        }
    }
}

// ---------------- attention v3: f32x2-packed microkernels ---------------------
#define AP   145
#define VP   68
#define QT_OFF 0
#define KT_OFF (64 * AP)
#define V_OFF  (2 * 64 * AP)
#define PT_OFF (2 * 64 * AP + 144 * VP)
#define ATTN_SMEM_FLOATS (2 * 64 * AP + 144 * VP + 144 * AP)
#define ATTN_SMEM_BYTES  (ATTN_SMEM_FLOATS * 4)

__global__ __launch_bounds__(256, 1)
void attn_kernel(const float* __restrict__ q, const float* __restrict__ kv,
                 float* __restrict__ o)
{
    extern __shared__ float sm[];
    float* Qt = sm + QT_OFF;
    float* Kt = sm + KT_OFF;
    float* Vs = sm + V_OFF;
    float* Pt = sm + PT_OFF;
    float* red = Pt;

    const int b = blockIdx.x >> 3;
    const int h = blockIdx.x & 7;
    const int t = threadIdx.x;
    const int ty = t >> 4;
    const int tx = t & 15;

    const float* qb = q  + (size_t)b * 144 * 512  + h * 64;
    const float* kb = kv + (size_t)b * 144 * 1024 + h * 64;
    const float* vb = kb + 512;

    for (int i = t; i < 144 * 64; i += 256) {
        int r = i >> 6, k = i & 63;
        Qt[k * AP + r] = qb[(size_t)r * 512 + k] * SCALE_;
        Kt[k * AP + r] = kb[(size_t)r * 1024 + k];
    }
    for (int i = t; i < 144 * 16; i += 256) {
        int n = i >> 4, cc = (i & 15) << 2;
        *(float4*)(Vs + n * VP + cc) = *(const float4*)(vb + (size_t)n * 1024 + cc);
    }
    __syncthreads();

    // ---- QK with f32x2: acc2[i][jp] packs cols (2jp, 2jp+1); acc8[i] = col 8 ----
    unsigned long long acc2[9][4];
    float acc8[9];
#pragma unroll
    for (int i = 0; i < 9; i++) {
#pragma unroll
        for (int jp = 0; jp < 4; jp++) acc2[i][jp] = 0ull;
        acc8[i] = 0.f;
    }

    const float* Qb = Qt + ty * 9;
    const float* Kb = Kt + tx * 9;
#pragma unroll 2
    for (int k = 0; k < 64; k++) {
        float qv[9], kvv[9];
#pragma unroll
        for (int i = 0; i < 9; i++) qv[i]  = Qb[k * AP + i];
#pragma unroll
        for (int j = 0; j < 9; j++) kvv[j] = Kb[k * AP + j];
        unsigned long long kp[4] = { pack2(kvv[0], kvv[1]), pack2(kvv[2], kvv[3]),
                                     pack2(kvv[4], kvv[5]), pack2(kvv[6], kvv[7]) };
#pragma unroll
        for (int i = 0; i < 9; i++) {
            unsigned long long qd = pack2(qv[i], qv[i]);
#pragma unroll
            for (int jp = 0; jp < 4; jp++) fma2(acc2[i][jp], qd, kp[jp]);
            acc8[i] += qv[i] * kvv[8];
        }
    }

    // expand into s[9][9]
    float s[9][9];
#pragma unroll
    for (int i = 0; i < 9; i++) {
#pragma unroll
        for (int jp = 0; jp < 4; jp++) {
            float2 u = unpack2(acc2[i][jp]);
            s[i][2 * jp]     = u.x;
            s[i][2 * jp + 1] = u.y;
        }
        s[i][8] = acc8[i];
    }

    // ---- softmax ----
#pragma unroll
    for (int i = 0; i < 9; i++) {
        float m = s[i][0];
#pragma unroll
        for (int j = 1; j < 9; j++) m = fmaxf(m, s[i][j]);
        red[(ty * 9 + i) * 17 + tx] = m;
    }
    __syncthreads();
    float mrow[9];
#pragma unroll
    for (int i = 0; i < 9; i++) {
        const float* rr = red + (ty * 9 + i) * 17;
        float m = rr[0];
#pragma unroll
        for (int u = 1; u < 16; u++) m = fmaxf(m, rr[u]);
        mrow[i] = m;
    }
    __syncthreads();
#pragma unroll
    for (int i = 0; i < 9; i++) {
        float sum = 0.f;
#pragma unroll
        for (int j = 0; j < 9; j++) {
            float e = __expf(s[i][j] - mrow[i]);
            s[i][j] = e;
            sum += e;
        }
        red[(ty * 9 + i) * 17 + tx] = sum;
    }
    __syncthreads();
    float inv[9];
#pragma unroll
    for (int i = 0; i < 9; i++) {
        const float* rr = red + (ty * 9 + i) * 17;
        float sum = rr[0];
#pragma unroll
        for (int u = 1; u < 16; u++) sum += rr[u];
        inv[i] = 1.f / sum;
    }
    __syncthreads();

#pragma unroll
    for (int j = 0; j < 9; j++)
#pragma unroll
        for (int i = 0; i < 9; i++)
            Pt[(tx * 9 + j) * AP + (ty * 9 + i)] = s[i][j];
    __syncthreads();

    // ---- PV with f32x2: out2[i][0]=(d0,d1), out2[i][1]=(d2,d3) ----
    unsigned long long out2[9][2];
#pragma unroll
    for (int i = 0; i < 9; i++) { out2[i][0] = 0ull; out2[i][1] = 0ull; }

    const float* Pb = Pt + ty * 9;
#pragma unroll 2
    for (int j = 0; j < 144; j++) {
        float pv[9];
#pragma unroll
        for (int i = 0; i < 9; i++) pv[i] = Pb[j * AP + i];
        float4 vv = *(const float4*)(Vs + j * VP + tx * 4);
        unsigned long long v01 = pack2(vv.x, vv.y);
        unsigned long long v23 = pack2(vv.z, vv.w);
#pragma unroll
        for (int i = 0; i < 9; i++) {
            unsigned long long pd = pack2(pv[i], pv[i]);
            fma2(out2[i][0], pd, v01);
            fma2(out2[i][1], pd, v23);
        }
    }

    float* ob = o + (size_t)b * 144 * 512 + h * 64;
#pragma unroll
    for (int i = 0; i < 9; i++) {
        int r = ty * 9 + i;
        float2 o01 = unpack2(out2[i][0]);
        float2 o23 = unpack2(out2[i][1]);
        *(float4*)(ob + (size_t)r * 512 + tx * 4) =
            make_float4(o01.x * inv[i], o01.y * inv[i],
                        o23.x * inv[i], o23.y * inv[i]);
    }
}

// ---------------- launch -------------------------------------------------------
extern "C" void kernel_launch(void* const* d_in, const int* in_sizes, int n_in,
                              void* d_out, int out_size)
{
    const float* x      = (const float*)d_in[0];
    const float* topo   = (const float*)d_in[1];
    const float* kv_w   = (const float*)d_in[2];
    const float* q_w    = (const float*)d_in[3];
    const float* proj_w = (const float*)d_in[4];
    const float* proj_b = (const float*)d_in[5];
    const int*   is_end = (const int*)d_in[6];

    void *pkv, *pq, *patt, *pxte, *pxe, *pae, *pwkv, *pwq, *pwp;
    cudaGetSymbolAddress(&pkv,  g_kv);
    cudaGetSymbolAddress(&pq,   g_q);
    cudaGetSymbolAddress(&patt, g_att);
    cudaGetSymbolAddress(&pxte, g_xte);
    cudaGetSymbolAddress(&pxe,  g_xe);
    cudaGetSymbolAddress(&pae,  g_ae);
    cudaGetSymbolAddress(&pwkv, g_wkve);
    cudaGetSymbolAddress(&pwq,  g_wqe);
    cudaGetSymbolAddress(&pwp,  g_wpe);

    cudaFuncSetAttribute(attn_kernel, cudaFuncAttributeMaxDynamicSharedMemorySize,
                         ATTN_SMEM_BYTES);

    const long act4 = (long)M_ * 512 / 4;
    const long wkv4 = 1024L * 512 / 4;
    const long w4   = 512L * 512 / 4;
    const int  TB   = 256;

    split_dual_kernel<<<(unsigned)((act4 + TB - 1) / TB), TB>>>(
        (const float4*)x, (const float4*)topo, is_end,
        (__nv_bfloat16*)pxe, (__nv_bfloat16*)pxte, act4);
    split_bf16_kernel<<<(unsigned)((wkv4 + TB - 1) / TB), TB>>>(
        (const float4*)kv_w, (__nv_bfloat16*)pwkv, wkv4);
    split_bf16_kernel<<<(unsigned)((w4 + TB - 1) / TB), TB>>>(
        (const float4*)q_w, (__nv_bfloat16*)pwq, w4);
    split_bf16_kernel<<<(unsigned)((w4 + TB - 1) / TB), TB>>>(
        (const float4*)proj_w, (__nv_bfloat16*)pwp, w4);

    gemm_mma_kernel<<<dim3(8, 288), 256>>>(
        (const __nv_bfloat16*)pxte, (const __nv_bfloat16*)pwkv, nullptr, (float*)pkv, 1024);
    gemm_mma_kernel<<<dim3(4, 288), 256>>>(
        (const __nv_bfloat16*)pxe, (const __nv_bfloat16*)pwq, nullptr, (float*)pq, 512);
    attn_kernel<<<B_ * 8, 256, ATTN_SMEM_BYTES>>>((float*)pq, (float*)pkv, (float*)patt);
    split_bf16_kernel<<<(unsigned)((act4 + TB - 1) / TB), TB>>>(
        (const float4*)patt, (__nv_bfloat16*)pae, act4);
    gemm_mma_kernel<<<dim3(4, 288), 256>>>(
        (const __nv_bfloat16*)pae, (const __nv_bfloat16*)pwp, proj_b, (float*)d_out, 512);
}

// round 7
// speedup vs baseline: 1.4412x; 1.0755x over previous
#include <cuda_runtime.h>
#include <cuda_bf16.h>
#include <cstdint>

#define B_   256
#define N_   144
#define M_   (B_ * N_)            // 36864 rows
#define SCALE_ 0.125f             // 64^-0.5

// ---------------- scratch (device globals: allocation-free rule) -------------
__device__ float g_kv [(size_t)M_ * 1024];
__device__ float g_q  [(size_t)M_ * 512];
__device__ float g_att[(size_t)M_ * 512];

// bf16 hi|lo split operands: [rows, 1024] = [hi(512) | lo(512)]
__device__ __nv_bfloat16 g_xte [(size_t)M_ * 1024];   // x + is_end*topo
__device__ __nv_bfloat16 g_xe  [(size_t)M_ * 1024];   // x
__device__ __nv_bfloat16 g_ae  [(size_t)M_ * 1024];   // attention out
__device__ __nv_bfloat16 g_wkve[(size_t)1024 * 1024];
__device__ __nv_bfloat16 g_wqe [(size_t)512 * 1024];
__device__ __nv_bfloat16 g_wpe [(size_t)512 * 1024];

// ---------------- helpers ------------------------------------------------------
__device__ __forceinline__ uint32_t smem_u32(const void* p) {
    uint32_t a;
    asm("{ .reg .u64 t; cvta.to.shared.u64 t, %1; cvt.u32.u64 %0, t; }" : "=r"(a) : "l"(p));
    return a;
}
__device__ __forceinline__ void ldsm_x4(uint32_t& r0, uint32_t& r1, uint32_t& r2,
                                        uint32_t& r3, uint32_t addr) {
    asm volatile("ldmatrix.sync.aligned.m8n8.x4.shared.b16 {%0,%1,%2,%3}, [%4];"
                 : "=r"(r0), "=r"(r1), "=r"(r2), "=r"(r3) : "r"(addr));
}
__device__ __forceinline__ void mma_bf16(float* c, uint32_t a0, uint32_t a1,
                                         uint32_t a2, uint32_t a3,
                                         uint32_t b0, uint32_t b1) {
    asm volatile(
        "mma.sync.aligned.m16n8k16.row.col.f32.bf16.bf16.f32 "
        "{%0,%1,%2,%3}, {%4,%5,%6,%7}, {%8,%9}, {%0,%1,%2,%3};"
        : "+f"(c[0]), "+f"(c[1]), "+f"(c[2]), "+f"(c[3])
        : "r"(a0), "r"(a1), "r"(a2), "r"(a3), "r"(b0), "r"(b1));
}
__device__ __forceinline__ void split1(float v, __nv_bfloat16& h, __nv_bfloat16& l) {
    h = __float2bfloat16_rn(v);
    l = __float2bfloat16_rn(v - __bfloat162float(h));
}
__device__ __forceinline__ void cp16(uint32_t dst, const void* src) {
    asm volatile("cp.async.cg.shared.global [%0], [%1], 16;" :: "r"(dst), "l"(src));
}
// packed f32x2
__device__ __forceinline__ unsigned long long pack2(float lo, float hi) {
    unsigned long long r;
    asm("mov.b64 %0, {%1, %2};" : "=l"(r) : "f"(lo), "f"(hi));
    return r;
}
__device__ __forceinline__ void fma2(unsigned long long& d, unsigned long long a, unsigned long long b) {
    asm("fma.rn.f32x2 %0, %1, %2, %0;" : "+l"(d) : "l"(a), "l"(b));
}
__device__ __forceinline__ float2 unpack2(unsigned long long v) {
    float2 r;
    asm("mov.b64 {%0, %1}, %2;" : "=f"(r.x), "=f"(r.y) : "l"(v));
    return r;
}

// ---------------- fp32 -> bf16 hi/lo split (single stream) --------------------
__global__ __launch_bounds__(256)
void split_bf16_kernel(const float4* __restrict__ in, __nv_bfloat16* __restrict__ out,
                       long total4)
{
    long i = (long)blockIdx.x * blockDim.x + threadIdx.x;
    if (i >= total4) return;
    float4 a = in[i];
    long idx = i * 4;
    long row = idx >> 9;
    int  col = (int)(idx & 511);
    float v[4] = { a.x, a.y, a.z, a.w };
    __nv_bfloat16 h[4], l[4];
#pragma unroll
    for (int j = 0; j < 4; j++) split1(v[j], h[j], l[j]);
    __nv_bfloat16* base = out + row * 1024 + col;
    *(uint2*)(base)       = *(uint2*)h;
    *(uint2*)(base + 512) = *(uint2*)l;
}

// dual: oxe = split(x), oxte = split(x + f*topo)
__global__ __launch_bounds__(256)
void split_dual_kernel(const float4* __restrict__ x, const float4* __restrict__ topo,
                       const int* __restrict__ flag,
                       __nv_bfloat16* __restrict__ oxe, __nv_bfloat16* __restrict__ oxte,
                       long total4)
{
    long i = (long)blockIdx.x * blockDim.x + threadIdx.x;
    if (i >= total4) return;
    float4 a = x[i];
    float4 tp = topo[i];
    float f = (*flag != 0) ? 1.f : 0.f;
    long idx = i * 4;
    long row = idx >> 9;
    int  col = (int)(idx & 511);
    float v1[4] = { a.x, a.y, a.z, a.w };
    float v2[4] = { a.x + f * tp.x, a.y + f * tp.y, a.z + f * tp.z, a.w + f * tp.w };
    __nv_bfloat16 h[4], l[4];
#pragma unroll
    for (int j = 0; j < 4; j++) split1(v1[j], h[j], l[j]);
    __nv_bfloat16* b1 = oxe + row * 1024 + col;
    *(uint2*)(b1)       = *(uint2*)h;
    *(uint2*)(b1 + 512) = *(uint2*)l;
#pragma unroll
    for (int j = 0; j < 4; j++) split1(v2[j], h[j], l[j]);
    __nv_bfloat16* b2 = oxte + row * 1024 + col;
    *(uint2*)(b2)       = *(uint2*)h;
    *(uint2*)(b2 + 512) = *(uint2*)l;
}

// ---------------- mma.sync bf16 GEMM, cp.async double-buffered -----------------
// C[M x Nc] = A_split @ W_split^T (+bias). 24 chunks (3 passes x 8), per chunk
// stage A/B 128x64 bf16 tiles via cp.async into buffer c&1 while computing c-1.
#define GTILE   18432                     // 128 rows x 144 B
#define GBUF    (2 * GTILE)               // A + B per stage buffer
#define GEMM_SMEM (2 * GBUF)              // 73728, double buffered

__global__ __launch_bounds__(256, 2)
void gemm_mma_kernel(const __nv_bfloat16* __restrict__ A,
                     const __nv_bfloat16* __restrict__ Bw,
                     const float* __restrict__ bias,
                     float* __restrict__ C, int Nc)
{
    extern __shared__ __align__(128) char smem[];
    const uint32_t sbase = smem_u32(smem);

    const int t    = threadIdx.x;
    const int lane = t & 31;
    const int w    = t >> 5;
    const int wm   = w >> 2;
    const int wn   = w & 3;
    const int row0 = blockIdx.y * 128;
    const int col0 = blockIdx.x * 128;

    const uint32_t aLane = sbase + (uint32_t)(wm * 64 + (lane & 15)) * 144 + (lane >> 4) * 16;
    const uint32_t bLane = sbase + GTILE
                         + (uint32_t)(wn * 32 + (lane & 7) + ((lane >> 4) & 1) * 8) * 144
                         + ((lane >> 3) & 1) * 16;

    float acc[4][4][4];
#pragma unroll
    for (int mi = 0; mi < 4; mi++)
#pragma unroll
        for (int nj = 0; nj < 4; nj++)
#pragma unroll
            for (int e = 0; e < 4; e++) acc[mi][nj][e] = 0.f;

    // staging map: thread -> row rowT + j*32 (j=0..3), 16B column chunk chT
    const int rowT = t >> 3;
    const int chT  = t & 7;
    const __nv_bfloat16* Ag = A  + (size_t)(row0 + rowT) * 1024 + chT * 8;
    const __nv_bfloat16* Bg = Bw + (size_t)(col0 + rowT) * 1024 + chT * 8;
    const uint32_t stA = sbase + (uint32_t)rowT * 144 + chT * 16;
    const uint32_t stB = stA + GTILE;

    auto stage = [&](int c, uint32_t bufOff) {
        const int s  = c >> 3;
        const int k0 = (c & 7) * 64;
        const int aCol = ((s == 1) ? 512 : 0) + k0;
        const int bCol = ((s == 2) ? 512 : 0) + k0;
#pragma unroll
        for (int j = 0; j < 4; j++) {
            cp16(stA + bufOff + j * 32 * 144, Ag + (size_t)j * 32 * 1024 + aCol);
            cp16(stB + bufOff + j * 32 * 144, Bg + (size_t)j * 32 * 1024 + bCol);
        }
        asm volatile("cp.async.commit_group;" ::: "memory");
    };

    stage(0, 0);
    for (int c = 0; c < 24; c++) {
        asm volatile("cp.async.wait_group 0;" ::: "memory");
        __syncthreads();               // chunk c visible; prev compute done
        if (c < 23) stage(c + 1, (uint32_t)((c + 1) & 1) * GBUF);
        const uint32_t bufOff = (uint32_t)(c & 1) * GBUF;

#pragma unroll
        for (int ks = 0; ks < 4; ks++) {
            uint32_t ar[4][4], br[2][4];
#pragma unroll
            for (int mi = 0; mi < 4; mi++)
                ldsm_x4(ar[mi][0], ar[mi][1], ar[mi][2], ar[mi][3],
                        aLane + bufOff + (uint32_t)mi * 16 * 144 + ks * 32);
#pragma unroll
            for (int pj = 0; pj < 2; pj++)
                ldsm_x4(br[pj][0], br[pj][1], br[pj][2], br[pj][3],
                        bLane + bufOff + (uint32_t)pj * 16 * 144 + ks * 32);
#pragma unroll
            for (int mi = 0; mi < 4; mi++)
#pragma unroll
                for (int nj = 0; nj < 4; nj++) {
                    const int pj = nj >> 1, hb = (nj & 1) * 2;
                    mma_bf16(acc[mi][nj], ar[mi][0], ar[mi][1], ar[mi][2], ar[mi][3],
                             br[pj][hb], br[pj][hb + 1]);
                }
        }
    }

    const int rbase = row0 + wm * 64 + (lane >> 2);
    const int cbase = col0 + wn * 32 + (lane & 3) * 2;
#pragma unroll
    for (int mi = 0; mi < 4; mi++) {
#pragma unroll
        for (int nj = 0; nj < 4; nj++) {
            const int r  = rbase + mi * 16;
            const int cc = cbase + nj * 8;
            float b0 = 0.f, b1 = 0.f;
            if (bias) { b0 = bias[cc]; b1 = bias[cc + 1]; }
            *(float2*)(C + (size_t)r * Nc + cc) =
                make_float2(acc[mi][nj][0] + b0, acc[mi][nj][1] + b1);
            *(float2*)(C + (size_t)(r + 8) * Nc + cc) =
                make_float2(acc[mi][nj][2] + b0, acc[mi][nj][3] + b1);
        }
    }
}

// ---------------- attention v3 (unchanged from round 6) -----------------------
#define AP   145
#define VP   68
#define QT_OFF 0
#define KT_OFF (64 * AP)
#define V_OFF  (2 * 64 * AP)
#define PT_OFF (2 * 64 * AP + 144 * VP)
#define ATTN_SMEM_FLOATS (2 * 64 * AP + 144 * VP + 144 * AP)
#define ATTN_SMEM_BYTES  (ATTN_SMEM_FLOATS * 4)

__global__ __launch_bounds__(256, 1)
void attn_kernel(const float* __restrict__ q, const float* __restrict__ kv,
                 float* __restrict__ o)
{
    extern __shared__ float sm[];
    float* Qt = sm + QT_OFF;
    float* Kt = sm + KT_OFF;
    float* Vs = sm + V_OFF;
    float* Pt = sm + PT_OFF;
    float* red = Pt;

    const int b = blockIdx.x >> 3;
    const int h = blockIdx.x & 7;
    const int t = threadIdx.x;
    const int ty = t >> 4;
    const int tx = t & 15;

    const float* qb = q  + (size_t)b * 144 * 512  + h * 64;
    const float* kb = kv + (size_t)b * 144 * 1024 + h * 64;
    const float* vb = kb + 512;

    for (int i = t; i < 144 * 64; i += 256) {
        int r = i >> 6, k = i & 63;
        Qt[k * AP + r] = qb[(size_t)r * 512 + k] * SCALE_;
        Kt[k * AP + r] = kb[(size_t)r * 1024 + k];
    }
    for (int i = t; i < 144 * 16; i += 256) {
        int n = i >> 4, cc = (i & 15) << 2;
        *(float4*)(Vs + n * VP + cc) = *(const float4*)(vb + (size_t)n * 1024 + cc);
    }
    __syncthreads();

    unsigned long long acc2[9][4];
    float acc8[9];
#pragma unroll
    for (int i = 0; i < 9; i++) {
#pragma unroll
        for (int jp = 0; jp < 4; jp++) acc2[i][jp] = 0ull;
        acc8[i] = 0.f;
    }

    const float* Qb = Qt + ty * 9;
    const float* Kb = Kt + tx * 9;
#pragma unroll 2
    for (int k = 0; k < 64; k++) {
        float qv[9], kvv[9];
#pragma unroll
        for (int i = 0; i < 9; i++) qv[i]  = Qb[k * AP + i];
#pragma unroll
        for (int j = 0; j < 9; j++) kvv[j] = Kb[k * AP + j];
        unsigned long long kp[4] = { pack2(kvv[0], kvv[1]), pack2(kvv[2], kvv[3]),
                                     pack2(kvv[4], kvv[5]), pack2(kvv[6], kvv[7]) };
#pragma unroll
        for (int i = 0; i < 9; i++) {
            unsigned long long qd = pack2(qv[i], qv[i]);
#pragma unroll
            for (int jp = 0; jp < 4; jp++) fma2(acc2[i][jp], qd, kp[jp]);
            acc8[i] += qv[i] * kvv[8];
        }
    }

    float s[9][9];
#pragma unroll
    for (int i = 0; i < 9; i++) {
#pragma unroll
        for (int jp = 0; jp < 4; jp++) {
            float2 u = unpack2(acc2[i][jp]);
            s[i][2 * jp]     = u.x;
            s[i][2 * jp + 1] = u.y;
        }
        s[i][8] = acc8[i];
    }

#pragma unroll
    for (int i = 0; i < 9; i++) {
        float m = s[i][0];
#pragma unroll
        for (int j = 1; j < 9; j++) m = fmaxf(m, s[i][j]);
        red[(ty * 9 + i) * 17 + tx] = m;
    }
    __syncthreads();
    float mrow[9];
#pragma unroll
    for (int i = 0; i < 9; i++) {
        const float* rr = red + (ty * 9 + i) * 17;
        float m = rr[0];
#pragma unroll
        for (int u = 1; u < 16; u++) m = fmaxf(m, rr[u]);
        mrow[i] = m;
    }
    __syncthreads();
#pragma unroll
    for (int i = 0; i < 9; i++) {
        float sum = 0.f;
#pragma unroll
        for (int j = 0; j < 9; j++) {
            float e = __expf(s[i][j] - mrow[i]);
            s[i][j] = e;
            sum += e;
        }
        red[(ty * 9 + i) * 17 + tx] = sum;
    }
    __syncthreads();
    float inv[9];
#pragma unroll
    for (int i = 0; i < 9; i++) {
        const float* rr = red + (ty * 9 + i) * 17;
        float sum = rr[0];
#pragma unroll
        for (int u = 1; u < 16; u++) sum += rr[u];
        inv[i] = 1.f / sum;
    }
    __syncthreads();

#pragma unroll
    for (int j = 0; j < 9; j++)
#pragma unroll
        for (int i = 0; i < 9; i++)
            Pt[(tx * 9 + j) * AP + (ty * 9 + i)] = s[i][j];
    __syncthreads();

    unsigned long long out2[9][2];
#pragma unroll
    for (int i = 0; i < 9; i++) { out2[i][0] = 0ull; out2[i][1] = 0ull; }

    const float* Pb = Pt + ty * 9;
#pragma unroll 2
    for (int j = 0; j < 144; j++) {
        float pv[9];
#pragma unroll
        for (int i = 0; i < 9; i++) pv[i] = Pb[j * AP + i];
        float4 vv = *(const float4*)(Vs + j * VP + tx * 4);
        unsigned long long v01 = pack2(vv.x, vv.y);
        unsigned long long v23 = pack2(vv.z, vv.w);
#pragma unroll
        for (int i = 0; i < 9; i++) {
            unsigned long long pd = pack2(pv[i], pv[i]);
            fma2(out2[i][0], pd, v01);
            fma2(out2[i][1], pd, v23);
        }
    }

    float* ob = o + (size_t)b * 144 * 512 + h * 64;
#pragma unroll
    for (int i = 0; i < 9; i++) {
        int r = ty * 9 + i;
        float2 o01 = unpack2(out2[i][0]);
        float2 o23 = unpack2(out2[i][1]);
        *(float4*)(ob + (size_t)r * 512 + tx * 4) =
            make_float4(o01.x * inv[i], o01.y * inv[i],
                        o23.x * inv[i], o23.y * inv[i]);
    }
}

// ---------------- launch -------------------------------------------------------
extern "C" void kernel_launch(void* const* d_in, const int* in_sizes, int n_in,
                              void* d_out, int out_size)
{
    const float* x      = (const float*)d_in[0];
    const float* topo   = (const float*)d_in[1];
    const float* kv_w   = (const float*)d_in[2];
    const float* q_w    = (const float*)d_in[3];
    const float* proj_w = (const float*)d_in[4];
    const float* proj_b = (const float*)d_in[5];
    const int*   is_end = (const int*)d_in[6];

    void *pkv, *pq, *patt, *pxte, *pxe, *pae, *pwkv, *pwq, *pwp;
    cudaGetSymbolAddress(&pkv,  g_kv);
    cudaGetSymbolAddress(&pq,   g_q);
    cudaGetSymbolAddress(&patt, g_att);
    cudaGetSymbolAddress(&pxte, g_xte);
    cudaGetSymbolAddress(&pxe,  g_xe);
    cudaGetSymbolAddress(&pae,  g_ae);
    cudaGetSymbolAddress(&pwkv, g_wkve);
    cudaGetSymbolAddress(&pwq,  g_wqe);
    cudaGetSymbolAddress(&pwp,  g_wpe);

    cudaFuncSetAttribute(attn_kernel, cudaFuncAttributeMaxDynamicSharedMemorySize,
                         ATTN_SMEM_BYTES);
    cudaFuncSetAttribute(gemm_mma_kernel, cudaFuncAttributeMaxDynamicSharedMemorySize,
                         GEMM_SMEM);

    const long act4 = (long)M_ * 512 / 4;
    const long wkv4 = 1024L * 512 / 4;
    const long w4   = 512L * 512 / 4;
    const int  TB   = 256;

    split_dual_kernel<<<(unsigned)((act4 + TB - 1) / TB), TB>>>(
        (const float4*)x, (const float4*)topo, is_end,
        (__nv_bfloat16*)pxe, (__nv_bfloat16*)pxte, act4);
    split_bf16_kernel<<<(unsigned)((wkv4 + TB - 1) / TB), TB>>>(
        (const float4*)kv_w, (__nv_bfloat16*)pwkv, wkv4);
    split_bf16_kernel<<<(unsigned)((w4 + TB - 1) / TB), TB>>>(
        (const float4*)q_w, (__nv_bfloat16*)pwq, w4);
    split_bf16_kernel<<<(unsigned)((w4 + TB - 1) / TB), TB>>>(
        (const float4*)proj_w, (__nv_bfloat16*)pwp, w4);

    gemm_mma_kernel<<<dim3(8, 288), 256, GEMM_SMEM>>>(
        (const __nv_bfloat16*)pxte, (const __nv_bfloat16*)pwkv, nullptr, (float*)pkv, 1024);
    gemm_mma_kernel<<<dim3(4, 288), 256, GEMM_SMEM>>>(
        (const __nv_bfloat16*)pxe, (const __nv_bfloat16*)pwq, nullptr, (float*)pq, 512);
    attn_kernel<<<B_ * 8, 256, ATTN_SMEM_BYTES>>>((float*)pq, (float*)pkv, (float*)patt);
    split_bf16_kernel<<<(unsigned)((act4 + TB - 1) / TB), TB>>>(
        (const float4*)patt, (__nv_bfloat16*)pae, act4);
    gemm_mma_kernel<<<dim3(4, 288), 256, GEMM_SMEM>>>(
        (const __nv_bfloat16*)pae, (const __nv_bfloat16*)pwp, proj_b, (float*)d_out, 512);
}